// round 6
// baseline (speedup 1.0000x reference)
#include <cuda_runtime.h>
#include <math.h>

// ---------------------------------------------------------------------------
// VQ-VAE forward.  B=16, L=156, P=8, H=W=128, codebook 512x8.
// R4: back to LDG+STS staging (cp.async regressed: <32 ops/thread + L1 bypass),
//     pre-packed paired weights kept, 1-row blocks (16 accs/thread) for
//     3 CTAs/SM occupancy.
// ---------------------------------------------------------------------------

#define BATCH 16
#define HW    16384   // 128*128

typedef unsigned long long u64;

__device__ __forceinline__ u64 pack2(float lo, float hi) {
    u64 r; asm("mov.b64 %0, {%1, %2};" : "=l"(r) : "f"(lo), "f"(hi)); return r;
}
__device__ __forceinline__ void fma2(u64 &d, u64 a, u64 b) {
    asm("fma.rn.f32x2 %0, %1, %2, %0;" : "+l"(d) : "l"(a), "l"(b));
}
__device__ __forceinline__ float2 unpk(u64 v) {
    float lo, hi; asm("mov.b64 {%0, %1}, %2;" : "=f"(lo), "=f"(hi) : "l"(v));
    return make_float2(lo, hi);
}

// Static device scratch (allocation-free rule).
__device__ float g_z1[BATCH * 128 * HW];
__device__ float g_z2[BATCH *  64 * HW];
__device__ float g_z3[BATCH *   8 * HW];
__device__ float g_q [BATCH *   8 * HW];
__device__ float g_y1[BATCH *  64 * HW];
__device__ float g_y2[BATCH * 128 * HW];
// packed paired weights: [chunk][cp][kc*9+tap] u64 {w[2cp], w[2cp+1]}
__device__ u64 g_pw_e1[20 * 64 * 72];
__device__ u64 g_pw_e2[16 * 32 * 72];
__device__ u64 g_pw_e3[ 8 *  8 * 72];
__device__ u64 g_pw_d1[ 1 * 32 * 72];
__device__ u64 g_pw_d2[ 8 * 64 * 72];
__device__ u64 g_pw_d3[16 * 80 * 72];
__device__ double g_part[256];

// ---------------------------------------------------------------------------
// Pack weights into [chunk][cp][kc*9+tap] u64 pairs.  transposed=1 handles
// ConvTranspose (in,out,kh,kw) with spatial flip: tap' = 8 - tap.
// ---------------------------------------------------------------------------
__global__ void pack_weights(const float* __restrict__ w, u64* __restrict__ pw,
                             int CIN, int COUT, int CP_PAD, int transposed) {
    int idx = blockIdx.x * 256 + threadIdx.x;
    int CHUNKS = (CIN + 7) / 8;
    int total = CHUNKS * CP_PAD * 72;
    if (idx >= total) return;
    int chunk = idx / (CP_PAD * 72);
    int rem   = idx % (CP_PAD * 72);
    int cp    = rem / 72;
    int rem2  = rem % 72;
    int kc    = rem2 / 9;
    int tap   = rem2 % 9;
    int ci    = chunk * 8 + kc;
    int co0 = 2 * cp, co1 = 2 * cp + 1;
    float v0 = 0.f, v1 = 0.f;
    if (ci < CIN) {
        if (transposed) {
            if (co0 < COUT) v0 = w[((size_t)ci * COUT + co0) * 9 + (8 - tap)];
            if (co1 < COUT) v1 = w[((size_t)ci * COUT + co1) * 9 + (8 - tap)];
        } else {
            if (co0 < COUT) v0 = w[((size_t)co0 * CIN + ci) * 9 + tap];
            if (co1 < COUT) v1 = w[((size_t)co1 * CIN + ci) * 9 + tap];
        }
    }
    pw[idx] = pack2(v0, v1);
}

__device__ __forceinline__ float apply_act(float v, int ACT) {
    if (ACT == 1) return fmaxf(v, 0.f);
    if (ACT == 2) return 1.f / (1.f + __expf(-v));
    return v;
}

// ---------------------------------------------------------------------------
// Packed-f32x2 3x3 same-conv.  Block = (n, output row h, MT co at CO_OFF+by*MT).
// 256 thr: lane -> 4 consecutive px (p0=4*lane), cg=tid>>5 -> co-pair group.
// Accumulator f32x2 lanes carry (co, co+1).  16 u64 accs/thread -> low regs,
// 3 CTAs/SM.  smem input row: x[gc] at float idx gc+4; halos idx 3 & 132
// pre-zeroed once and never overwritten.
// ---------------------------------------------------------------------------
template<int CIN, int COUT, int MT, int ACT, int CO_OFF, int CP_PAD>
__global__ __launch_bounds__(256, 3)
void conv3x3r(const float* __restrict__ in, const u64* __restrict__ pw,
              const float* __restrict__ bias, float* __restrict__ out) {
    constexpr int KC     = 8;
    constexpr int NCP    = MT / 16;           // co-pairs per thread
    constexpr int NCPG   = MT / 2;            // co-pairs per block
    constexpr int CHUNKS = (CIN + KC - 1) / KC;
    constexpr int ROWSTR = 136;

    __shared__ float s_in[KC * 3 * ROWSTR];
    __shared__ u64   s_w[NCPG * 72];

    const int n       = blockIdx.z;
    const int h       = blockIdx.x;
    const int co_base = CO_OFF + blockIdx.y * MT;
    const int cp_base = co_base / 2;
    const int tid     = threadIdx.x;
    const int lane    = tid & 31;
    const int cg      = tid >> 5;
    const int p0      = lane * 4;

    const float* inN = in + (size_t)n * CIN * HW;

    // zero halo columns (written once, never overwritten by staging)
    if (tid < KC * 3) {
        float* row = s_in + tid * ROWSTR;
        row[0] = 0.f; row[1] = 0.f; row[2] = 0.f; row[3] = 0.f;
        row[132] = 0.f; row[133] = 0.f; row[134] = 0.f; row[135] = 0.f;
    }

    u64 acc[NCP][4];
#pragma unroll
    for (int c = 0; c < NCP; c++)
#pragma unroll
        for (int k = 0; k < 4; k++) acc[c][k] = 0ull;

    for (int chunk = 0; chunk < CHUNKS; chunk++) {
        // ---- stage input: KC ch x 3 rows x 32 float4
        for (int s4 = tid; s4 < KC * 3 * 32; s4 += 256) {
            int kc = s4 / 96;
            int r  = (s4 / 32) % 3;
            int s  = s4 & 31;
            int ci = chunk * KC + kc;
            int gh = h - 1 + r;
            float4 v = make_float4(0.f, 0.f, 0.f, 0.f);
            if (ci < CIN && gh >= 0 && gh < 128)
                v = *(const float4*)(inN + (size_t)ci * HW + gh * 128 + s * 4);
            *(float4*)(s_in + (kc * 3 + r) * ROWSTR + 4 + s * 4) = v;
        }
        // ---- stage weights: NCPG*72 u64 contiguous (L1-cached LDG)
        {
            const float4* wsrc = (const float4*)(pw + ((size_t)chunk * CP_PAD + cp_base) * 72);
            float4* wdst = (float4*)s_w;
            for (int s = tid; s < NCPG * 36; s += 256) wdst[s] = wsrc[s];
        }
        __syncthreads();

        for (int kc = 0; kc < KC; kc++) {
#pragma unroll
            for (int dh = 0; dh < 3; dh++) {
                const float* row = s_in + (kc * 3 + dh) * ROWSTR;
                float4 A = *(const float4*)(row + p0);
                float4 B = *(const float4*)(row + p0 + 4);
                float4 C = *(const float4*)(row + p0 + 8);
                u64 dup[6];
                dup[0] = pack2(A.w, A.w);
                dup[1] = pack2(B.x, B.x);
                dup[2] = pack2(B.y, B.y);
                dup[3] = pack2(B.z, B.z);
                dup[4] = pack2(B.w, B.w);
                dup[5] = pack2(C.x, C.x);
#pragma unroll
                for (int dw = 0; dw < 3; dw++) {
#pragma unroll
                    for (int cp = 0; cp < NCP; cp++) {
                        u64 w = s_w[(cg * NCP + cp) * 72 + kc * 9 + dh * 3 + dw];
#pragma unroll
                        for (int k = 0; k < 4; k++)
                            fma2(acc[cp][k], w, dup[k + dw]);
                    }
                }
            }
        }
        __syncthreads();
    }

    // ---- epilogue: unpack, bias, activation, vectorized stores
#pragma unroll
    for (int cp = 0; cp < NCP; cp++) {
        int co0 = co_base + 2 * (cg * NCP + cp);
        float2 r0 = unpk(acc[cp][0]);
        float2 r1 = unpk(acc[cp][1]);
        float2 r2 = unpk(acc[cp][2]);
        float2 r3 = unpk(acc[cp][3]);
        size_t rowoff = (size_t)h * 128 + p0;
        if (co0 < COUT) {
            float b = bias[co0];
            float4 o;
            o.x = apply_act(r0.x + b, ACT);
            o.y = apply_act(r1.x + b, ACT);
            o.z = apply_act(r2.x + b, ACT);
            o.w = apply_act(r3.x + b, ACT);
            *(float4*)&out[((size_t)n * COUT + co0) * HW + rowoff] = o;
        }
        if (co0 + 1 < COUT) {
            float b = bias[co0 + 1];
            float4 o;
            o.x = apply_act(r0.y + b, ACT);
            o.y = apply_act(r1.y + b, ACT);
            o.z = apply_act(r2.y + b, ACT);
            o.w = apply_act(r3.y + b, ACT);
            *(float4*)&out[((size_t)n * COUT + (co0 + 1)) * HW + rowoff] = o;
        }
    }
}

// ---------------------------------------------------------------------------
// Vector quantizer (groups of 8 along W, torch .view semantics).
// ---------------------------------------------------------------------------
__global__ __launch_bounds__(256)
void vq_kernel(const float* __restrict__ z, const float* __restrict__ emb,
               float* __restrict__ q, double* __restrict__ part) {
    __shared__ float  s_e[512 * 8];
    __shared__ float  s_hn[512];
    __shared__ double s_red[256];

    const int tid = threadIdx.x;
    for (int i = tid; i < 4096; i += 256) s_e[i] = emb[i];
    __syncthreads();
    for (int k = tid; k < 512; k += 256) {
        float s = 0.f;
#pragma unroll
        for (int j = 0; j < 8; j++) { float e = s_e[k * 8 + j]; s += e * e; }
        s_hn[k] = 0.5f * s;
    }
    __syncthreads();

    const int base = blockIdx.x * 1024 + tid;
    float v[4][8];
#pragma unroll
    for (int u = 0; u < 4; u++) {
        int vi = base + u * 256;
        float4 a = ((const float4*)z)[vi * 2];
        float4 b = ((const float4*)z)[vi * 2 + 1];
        v[u][0] = a.x; v[u][1] = a.y; v[u][2] = a.z; v[u][3] = a.w;
        v[u][4] = b.x; v[u][5] = b.y; v[u][6] = b.z; v[u][7] = b.w;
    }

    float best[4] = {3.4e38f, 3.4e38f, 3.4e38f, 3.4e38f};
    int   bk[4]   = {0, 0, 0, 0};
    for (int k = 0; k < 512; k++) {
        float e0 = s_e[k * 8 + 0], e1 = s_e[k * 8 + 1], e2 = s_e[k * 8 + 2], e3 = s_e[k * 8 + 3];
        float e4 = s_e[k * 8 + 4], e5 = s_e[k * 8 + 5], e6 = s_e[k * 8 + 6], e7 = s_e[k * 8 + 7];
        float hn = s_hn[k];
#pragma unroll
        for (int u = 0; u < 4; u++) {
            float dot = e0 * v[u][0] + e1 * v[u][1] + e2 * v[u][2] + e3 * v[u][3]
                      + e4 * v[u][4] + e5 * v[u][5] + e6 * v[u][6] + e7 * v[u][7];
            float sc = hn - dot;
            if (sc < best[u]) { best[u] = sc; bk[u] = k; }
        }
    }

    float sq = 0.f;
#pragma unroll
    for (int u = 0; u < 4; u++) {
        int vi = base + u * 256;
        int kb = bk[u];
        float4 o1, o2;
        o1.x = s_e[kb * 8 + 0]; o1.y = s_e[kb * 8 + 1];
        o1.z = s_e[kb * 8 + 2]; o1.w = s_e[kb * 8 + 3];
        o2.x = s_e[kb * 8 + 4]; o2.y = s_e[kb * 8 + 5];
        o2.z = s_e[kb * 8 + 6]; o2.w = s_e[kb * 8 + 7];
#pragma unroll
        for (int j = 0; j < 8; j++) {
            float d = s_e[kb * 8 + j] - v[u][j];
            sq += d * d;
        }
        ((float4*)q)[vi * 2]     = o1;
        ((float4*)q)[vi * 2 + 1] = o2;
    }

    s_red[tid] = (double)sq;
    __syncthreads();
    for (int o = 128; o > 0; o >>= 1) {
        if (tid < o) s_red[tid] += s_red[tid + o];
        __syncthreads();
    }
    if (tid == 0) part[blockIdx.x] = s_red[0];
}

__global__ void finalize_loss(const double* __restrict__ part, float* __restrict__ outp) {
    __shared__ double s[256];
    int tid = threadIdx.x;
    s[tid] = part[tid];
    __syncthreads();
    for (int o = 128; o > 0; o >>= 1) {
        if (tid < o) s[tid] += s[tid + o];
        __syncthreads();
    }
    if (tid == 0) *outp = (float)(1.25 * s[0] / 2097152.0);
}

// ---------------------------------------------------------------------------
extern "C" void kernel_launch(void* const* d_in, const int* in_sizes, int n_in,
                              void* d_out, int out_size) {
    (void)in_sizes; (void)n_in;
    const float* x   = (const float*)d_in[0];
    const float* e1w = (const float*)d_in[1];
    const float* e1b = (const float*)d_in[2];
    const float* e2w = (const float*)d_in[3];
    const float* e2b = (const float*)d_in[4];
    const float* e3w = (const float*)d_in[5];
    const float* e3b = (const float*)d_in[6];
    const float* emb = (const float*)d_in[7];
    const float* d1w = (const float*)d_in[8];
    const float* d1b = (const float*)d_in[9];
    const float* d2w = (const float*)d_in[10];
    const float* d2b = (const float*)d_in[11];
    const float* d3w = (const float*)d_in[12];
    const float* d3b = (const float*)d_in[13];
    float* out = (float*)d_out;

    void *z1, *z2, *z3, *q, *y1, *y2, *part;
    void *pw1, *pw2, *pw3, *pw4, *pw5, *pw6;
    cudaGetSymbolAddress(&z1,  g_z1);
    cudaGetSymbolAddress(&z2,  g_z2);
    cudaGetSymbolAddress(&z3,  g_z3);
    cudaGetSymbolAddress(&q,   g_q);
    cudaGetSymbolAddress(&y1,  g_y1);
    cudaGetSymbolAddress(&y2,  g_y2);
    cudaGetSymbolAddress(&pw1, g_pw_e1);
    cudaGetSymbolAddress(&pw2, g_pw_e2);
    cudaGetSymbolAddress(&pw3, g_pw_e3);
    cudaGetSymbolAddress(&pw4, g_pw_d1);
    cudaGetSymbolAddress(&pw5, g_pw_d2);
    cudaGetSymbolAddress(&pw6, g_pw_d3);
    cudaGetSymbolAddress(&part, g_part);

    // ---- weight packing (tiny)
    pack_weights<<<(20 * 64 * 72 + 255) / 256, 256>>>(e1w, (u64*)pw1, 156, 128, 64, 0);
    pack_weights<<<(16 * 32 * 72 + 255) / 256, 256>>>(e2w, (u64*)pw2, 128,  64, 32, 0);
    pack_weights<<<( 8 *  8 * 72 + 255) / 256, 256>>>(e3w, (u64*)pw3,  64,   8,  8, 0);
    pack_weights<<<( 1 * 32 * 72 + 255) / 256, 256>>>(d1w, (u64*)pw4,   8,  64, 32, 1);
    pack_weights<<<( 8 * 64 * 72 + 255) / 256, 256>>>(d2w, (u64*)pw5,  64, 128, 64, 1);
    pack_weights<<<(16 * 80 * 72 + 255) / 256, 256>>>(d3w, (u64*)pw6, 128, 156, 80, 1);

    // encoder
    conv3x3r<156, 128, 64, 1, 0, 64><<<dim3(128, 2, 16), 256>>>(x, (u64*)pw1, e1b, (float*)z1);
    conv3x3r<128,  64, 64, 1, 0, 32><<<dim3(128, 1, 16), 256>>>((float*)z1, (u64*)pw2, e2b, (float*)z2);
    conv3x3r< 64,   8, 16, 1, 0,  8><<<dim3(128, 1, 16), 256>>>((float*)z2, (u64*)pw3, e3b, (float*)z3);

    // vector quantizer + loss partials
    vq_kernel<<<256, 256>>>((const float*)z3, emb, (float*)q, (double*)part);

    // decoder
    conv3x3r<  8,  64, 64, 1, 0, 32><<<dim3(128, 1, 16), 256>>>((float*)q,  (u64*)pw4, d1b, (float*)y1);
    conv3x3r< 64, 128, 64, 1, 0, 64><<<dim3(128, 2, 16), 256>>>((float*)y1, (u64*)pw5, d2b, (float*)y2);
    conv3x3r<128, 156, 64, 2, 0,   80><<<dim3(128, 2, 16), 256>>>((float*)y2, (u64*)pw6, d3b, out);
    conv3x3r<128, 156, 32, 2, 128, 80><<<dim3(128, 1, 16), 256>>>((float*)y2, (u64*)pw6, d3b, out);

    finalize_loss<<<1, 256>>>((const double*)part, out + (out_size - 1));
}

// round 7
// speedup vs baseline: 1.3905x; 1.3905x over previous
#include <cuda_runtime.h>
#include <math.h>

// ---------------------------------------------------------------------------
// VQ-VAE forward.  B=16, L=156, P=8, H=W=128, codebook 512x8.
// R7: decoder convs on tensor pipe (mma.sync m16n8k8 tf32, rounded operands);
//     encoder stays on the proven FFMA2 path (protects VQ argmin exactness).
// ---------------------------------------------------------------------------

#define BATCH 16
#define HW    16384   // 128*128

typedef unsigned long long u64;

__device__ __forceinline__ u64 pack2(float lo, float hi) {
    u64 r; asm("mov.b64 %0, {%1, %2};" : "=l"(r) : "f"(lo), "f"(hi)); return r;
}
__device__ __forceinline__ void fma2(u64 &d, u64 a, u64 b) {
    asm("fma.rn.f32x2 %0, %1, %2, %0;" : "+l"(d) : "l"(a), "l"(b));
}
__device__ __forceinline__ float2 unpk(u64 v) {
    float lo, hi; asm("mov.b64 {%0, %1}, %2;" : "=f"(lo), "=f"(hi) : "l"(v));
    return make_float2(lo, hi);
}
__device__ __forceinline__ float to_tf32(float x) {
    unsigned u; asm("cvt.rna.tf32.f32 %0, %1;" : "=r"(u) : "f"(x));
    return __uint_as_float(u);
}
__device__ __forceinline__ void mma_tf32(float c[4], const float a[4], float2 b) {
    asm volatile("mma.sync.aligned.m16n8k8.row.col.f32.tf32.tf32.f32 "
        "{%0,%1,%2,%3}, {%4,%5,%6,%7}, {%8,%9}, {%0,%1,%2,%3};"
        : "+f"(c[0]), "+f"(c[1]), "+f"(c[2]), "+f"(c[3])
        : "r"(__float_as_uint(a[0])), "r"(__float_as_uint(a[1])),
          "r"(__float_as_uint(a[2])), "r"(__float_as_uint(a[3])),
          "r"(__float_as_uint(b.x)), "r"(__float_as_uint(b.y)));
}

// Static device scratch (allocation-free rule).
__device__ float g_z1[BATCH * 128 * HW];
__device__ float g_z2[BATCH *  64 * HW];
__device__ float g_z3[BATCH *   8 * HW];
__device__ float g_q [BATCH *   8 * HW];
__device__ float g_y1[BATCH *  64 * HW];
__device__ float g_y2[BATCH * 128 * HW];
// encoder packed paired weights: [chunk][cp][kc*9+tap] u64 {w[2cp], w[2cp+1]}
__device__ u64 g_pw_e1[20 * 64 * 72];
__device__ u64 g_pw_e2[16 * 32 * 72];
__device__ u64 g_pw_e3[ 8 *  8 * 72];
// decoder tf32 weights for mma: [chunk][tap 9][CO_PAD][8 ci-perm], perm p -> ci = (p>>1)+4*(p&1)
__device__ float g_mw_d1[ 1 * 9 *  64 * 8];
__device__ float g_mw_d2[ 8 * 9 * 128 * 8];
__device__ float g_mw_d3[16 * 9 * 160 * 8];
__device__ double g_part[256];

// ---------------------------------------------------------------------------
// One merged packing kernel (keeps launch count low; ncu -s 5 then lands on a
// decoder conv).  Encoder layout as before; decoder = tf32-rounded, ci-perm.
// ---------------------------------------------------------------------------
__device__ void pack_enc(const float* __restrict__ w, u64* __restrict__ pw,
                         int CIN, int COUT, int CP_PAD, int idx) {
    int cp    = (idx / 72) % CP_PAD;
    int chunk = (idx / 72) / CP_PAD;
    int rem2  = idx % 72;
    int kc    = rem2 / 9;
    int tap   = rem2 % 9;
    int ci    = chunk * 8 + kc;
    int co0 = 2 * cp, co1 = 2 * cp + 1;
    float v0 = 0.f, v1 = 0.f;
    if (ci < CIN) {
        if (co0 < COUT) v0 = w[((size_t)co0 * CIN + ci) * 9 + tap];
        if (co1 < COUT) v1 = w[((size_t)co1 * CIN + ci) * 9 + tap];
    }
    pw[idx] = pack2(v0, v1);
}

__device__ void pack_dec(const float* __restrict__ w, float* __restrict__ out,
                         int CIN, int COUT, int CO_PAD, int idx) {
    // idx -> [chunk][tap][co][p]
    int p     = idx & 7;
    int co    = (idx >> 3) % CO_PAD;
    int tap   = ((idx >> 3) / CO_PAD) % 9;
    int chunk = ((idx >> 3) / CO_PAD) / 9;
    int ci    = chunk * 8 + (p >> 1) + 4 * (p & 1);
    float v = 0.f;
    if (co < COUT && ci < CIN)
        v = w[((size_t)ci * COUT + co) * 9 + (8 - tap)];  // convT: IO-swap + flip
    out[idx] = to_tf32(v);
}

__global__ void pack_all(const float* e1w, const float* e2w, const float* e3w,
                         const float* d1w, const float* d2w, const float* d3w,
                         u64* pe1, u64* pe2, u64* pe3,
                         float* md1, float* md2, float* md3) {
    int idx = blockIdx.x * 256 + threadIdx.x;
    if (idx < 92160) { pack_enc(e1w, pe1, 156, 128, 64, idx); return; }
    idx -= 92160;
    if (idx < 36864) { pack_enc(e2w, pe2, 128, 64, 32, idx); return; }
    idx -= 36864;
    if (idx < 4608)  { pack_enc(e3w, pe3, 64, 8, 8, idx); return; }
    idx -= 4608;
    if (idx < 4608)  { pack_dec(d1w, md1, 8, 64, 64, idx); return; }
    idx -= 4608;
    if (idx < 73728) { pack_dec(d2w, md2, 64, 128, 128, idx); return; }
    idx -= 73728;
    if (idx < 184320) { pack_dec(d3w, md3, 128, 156, 160, idx); }
}

__device__ __forceinline__ float apply_act(float v, int ACT) {
    if (ACT == 1) return fmaxf(v, 0.f);
    if (ACT == 2) return 1.f / (1.f + __expf(-v));
    return v;
}

// ---------------------------------------------------------------------------
// Encoder: packed-f32x2 3x3 same-conv (R6, unchanged — protects VQ exactness).
// ---------------------------------------------------------------------------
template<int CIN, int COUT, int MT, int ACT, int CO_OFF, int CP_PAD>
__global__ __launch_bounds__(256, 3)
void conv3x3r(const float* __restrict__ in, const u64* __restrict__ pw,
              const float* __restrict__ bias, float* __restrict__ out) {
    constexpr int KC     = 8;
    constexpr int NCP    = MT / 16;
    constexpr int NCPG   = MT / 2;
    constexpr int CHUNKS = (CIN + KC - 1) / KC;
    constexpr int ROWSTR = 136;

    __shared__ float s_in[KC * 3 * ROWSTR];
    __shared__ u64   s_w[NCPG * 72];

    const int n       = blockIdx.z;
    const int h       = blockIdx.x;
    const int co_base = CO_OFF + blockIdx.y * MT;
    const int cp_base = co_base / 2;
    const int tid     = threadIdx.x;
    const int lane    = tid & 31;
    const int cg      = tid >> 5;
    const int p0      = lane * 4;

    const float* inN = in + (size_t)n * CIN * HW;

    if (tid < KC * 3) {
        float* row = s_in + tid * ROWSTR;
        row[0] = 0.f; row[1] = 0.f; row[2] = 0.f; row[3] = 0.f;
        row[132] = 0.f; row[133] = 0.f; row[134] = 0.f; row[135] = 0.f;
    }

    u64 acc[NCP][4];
#pragma unroll
    for (int c = 0; c < NCP; c++)
#pragma unroll
        for (int k = 0; k < 4; k++) acc[c][k] = 0ull;

    for (int chunk = 0; chunk < CHUNKS; chunk++) {
        for (int s4 = tid; s4 < KC * 3 * 32; s4 += 256) {
            int kc = s4 / 96;
            int r  = (s4 / 32) % 3;
            int s  = s4 & 31;
            int ci = chunk * KC + kc;
            int gh = h - 1 + r;
            float4 v = make_float4(0.f, 0.f, 0.f, 0.f);
            if (ci < CIN && gh >= 0 && gh < 128)
                v = *(const float4*)(inN + (size_t)ci * HW + gh * 128 + s * 4);
            *(float4*)(s_in + (kc * 3 + r) * ROWSTR + 4 + s * 4) = v;
        }
        {
            const float4* wsrc = (const float4*)(pw + ((size_t)chunk * CP_PAD + cp_base) * 72);
            float4* wdst = (float4*)s_w;
            for (int s = tid; s < NCPG * 36; s += 256) wdst[s] = wsrc[s];
        }
        __syncthreads();

        for (int kc = 0; kc < KC; kc++) {
#pragma unroll
            for (int dh = 0; dh < 3; dh++) {
                const float* row = s_in + (kc * 3 + dh) * ROWSTR;
                float4 A = *(const float4*)(row + p0);
                float4 B = *(const float4*)(row + p0 + 4);
                float4 C = *(const float4*)(row + p0 + 8);
                u64 dup[6];
                dup[0] = pack2(A.w, A.w);
                dup[1] = pack2(B.x, B.x);
                dup[2] = pack2(B.y, B.y);
                dup[3] = pack2(B.z, B.z);
                dup[4] = pack2(B.w, B.w);
                dup[5] = pack2(C.x, C.x);
#pragma unroll
                for (int dw = 0; dw < 3; dw++) {
#pragma unroll
                    for (int cp = 0; cp < NCP; cp++) {
                        u64 w = s_w[(cg * NCP + cp) * 72 + kc * 9 + dh * 3 + dw];
#pragma unroll
                        for (int k = 0; k < 4; k++)
                            fma2(acc[cp][k], w, dup[k + dw]);
                    }
                }
            }
        }
        __syncthreads();
    }

#pragma unroll
    for (int cp = 0; cp < NCP; cp++) {
        int co0 = co_base + 2 * (cg * NCP + cp);
        float2 r0 = unpk(acc[cp][0]);
        float2 r1 = unpk(acc[cp][1]);
        float2 r2 = unpk(acc[cp][2]);
        float2 r3 = unpk(acc[cp][3]);
        size_t rowoff = (size_t)h * 128 + p0;
        if (co0 < COUT) {
            float b = bias[co0];
            float4 o;
            o.x = apply_act(r0.x + b, ACT);
            o.y = apply_act(r1.x + b, ACT);
            o.z = apply_act(r2.x + b, ACT);
            o.w = apply_act(r3.x + b, ACT);
            *(float4*)&out[((size_t)n * COUT + co0) * HW + rowoff] = o;
        }
        if (co0 + 1 < COUT) {
            float b = bias[co0 + 1];
            float4 o;
            o.x = apply_act(r0.y + b, ACT);
            o.y = apply_act(r1.y + b, ACT);
            o.z = apply_act(r2.y + b, ACT);
            o.w = apply_act(r3.y + b, ACT);
            *(float4*)&out[((size_t)n * COUT + (co0 + 1)) * HW + rowoff] = o;
        }
    }
}

// ---------------------------------------------------------------------------
// Decoder: tf32 tensor-core conv (mma.sync m16n8k8).  C[px][co] accumulated
// as 9 shifted GEMMs per 8-ci chunk.  Block = (n, row h, MT co at CO_OFF).
// 8 warps: wm = warp&3 -> 32-px span, wn = warp>>2 -> MT/2 co span.
// Warp tile: 2 m-tiles (m16) x (MT/16) n-tiles (n8).
// A fragment (m16n8k8 tf32, row-major): a0(r,c) a1(r+8,c) a2(r,c+4) a3(r+8,c+4),
// r = pxbase + t/4, c = ci = t%4.  B: b0(k=t%4, n) b1(k=t%4+4, n), served by
// one LDS.64 from the ci-permuted weight layout.
// ---------------------------------------------------------------------------
template<int CIN, int COUT, int MT, int ACT, int CO_OFF, int CO_PAD>
__global__ __launch_bounds__(256, 3)
void convmma(const float* __restrict__ in, const float* __restrict__ mw,
             const float* __restrict__ bias, float* __restrict__ out) {
    constexpr int CHUNKS = CIN / 8;
    constexpr int ROWSTR = 136;
    constexpr int NT     = MT / 16;   // n-tiles per warp

    __shared__ float s_in[8 * 3 * ROWSTR];
    __shared__ float s_w[9 * MT * 8];

    const int n    = blockIdx.z;
    const int h    = blockIdx.x;
    const int cob0 = CO_OFF + blockIdx.y * MT;       // block co base (global)
    const int tid  = threadIdx.x;
    const int lane = tid & 31;
    const int warp = tid >> 5;
    const int wm   = warp & 3;
    const int wn   = warp >> 2;
    const int r4   = lane & 3;    // t%4
    const int r4h  = lane >> 2;   // t/4
    const int pxb  = wm * 32;
    const int col  = wn * (MT / 2);                  // warp co base (local)

    const float* inN = in + (size_t)n * CIN * HW;

    if (tid < 24) {
        float* row = s_in + tid * ROWSTR;
        row[0] = 0.f; row[1] = 0.f; row[2] = 0.f; row[3] = 0.f;
        row[132] = 0.f; row[133] = 0.f; row[134] = 0.f; row[135] = 0.f;
    }

    float C[2][NT][4];
#pragma unroll
    for (int mt = 0; mt < 2; mt++)
#pragma unroll
        for (int nt = 0; nt < NT; nt++)
#pragma unroll
            for (int k = 0; k < 4; k++) C[mt][nt][k] = 0.f;

    for (int chunk = 0; chunk < CHUNKS; chunk++) {
        // stage input slab (tf32-rounded)
        for (int s4 = tid; s4 < 8 * 3 * 32; s4 += 256) {
            int kc = s4 / 96;
            int r  = (s4 / 32) % 3;
            int s  = s4 & 31;
            int ci = chunk * 8 + kc;
            int gh = h - 1 + r;
            float4 v = make_float4(0.f, 0.f, 0.f, 0.f);
            if (gh >= 0 && gh < 128)
                v = *(const float4*)(inN + (size_t)ci * HW + gh * 128 + s * 4);
            v.x = to_tf32(v.x); v.y = to_tf32(v.y);
            v.z = to_tf32(v.z); v.w = to_tf32(v.w);
            *(float4*)(s_in + (kc * 3 + r) * ROWSTR + 4 + s * 4) = v;
        }
        // stage weights: [tap][MT co][8 perm] -- slice co range, contiguous per tap
        for (int s = tid; s < 9 * MT * 2; s += 256) {
            int tap = s / (MT * 2);
            int r   = s % (MT * 2);
            const float4* src = (const float4*)(mw +
                (((size_t)chunk * 9 + tap) * CO_PAD + cob0) * 8) + r;
            ((float4*)s_w)[tap * MT * 2 + r] = *src;
        }
        __syncthreads();

#pragma unroll
        for (int dh = 0; dh < 3; dh++) {
#pragma unroll
            for (int dw = 0; dw < 3; dw++) {
                const int tap = dh * 3 + dw;
                float a[2][4];
                {
                    const float* base = s_in + r4 * (3 * ROWSTR) + dh * ROWSTR
                                      + pxb + dw + 3 + r4h;
#pragma unroll
                    for (int mt = 0; mt < 2; mt++) {
                        a[mt][0] = base[mt * 16];
                        a[mt][1] = base[mt * 16 + 8];
                        a[mt][2] = base[4 * (3 * ROWSTR) + mt * 16];
                        a[mt][3] = base[4 * (3 * ROWSTR) + mt * 16 + 8];
                    }
                }
#pragma unroll
                for (int nt = 0; nt < NT; nt++) {
                    int co_l = col + nt * 8 + r4h;
                    float2 b = *(const float2*)(s_w + ((size_t)tap * MT + co_l) * 8 + r4 * 2);
#pragma unroll
                    for (int mt = 0; mt < 2; mt++)
                        mma_tf32(C[mt][nt], a[mt], b);
                }
            }
        }
        __syncthreads();
    }

    // epilogue: c0 (px, co) c1 (px, co+1) c2 (px+8, co) c3 (px+8, co+1)
#pragma unroll
    for (int mt = 0; mt < 2; mt++) {
#pragma unroll
        for (int nt = 0; nt < NT; nt++) {
            int px = pxb + mt * 16 + r4h;
            int co = cob0 + col + nt * 8 + r4 * 2;
            size_t o0 = (size_t)h * 128 + px;
            if (co < COUT) {
                float b = bias[co];
                float* op = out + ((size_t)n * COUT + co) * HW;
                op[o0]     = apply_act(C[mt][nt][0] + b, ACT);
                op[o0 + 8] = apply_act(C[mt][nt][2] + b, ACT);
            }
            if (co + 1 < COUT) {
                float b = bias[co + 1];
                float* op = out + ((size_t)n * COUT + co + 1) * HW;
                op[o0]     = apply_act(C[mt][nt][1] + b, ACT);
                op[o0 + 8] = apply_act(C[mt][nt][3] + b, ACT);
            }
        }
    }
}

// ---------------------------------------------------------------------------
// Vector quantizer (groups of 8 along W, torch .view semantics).
// ---------------------------------------------------------------------------
__global__ __launch_bounds__(256)
void vq_kernel(const float* __restrict__ z, const float* __restrict__ emb,
               float* __restrict__ q, double* __restrict__ part) {
    __shared__ float  s_e[512 * 8];
    __shared__ float  s_hn[512];
    __shared__ double s_red[256];

    const int tid = threadIdx.x;
    for (int i = tid; i < 4096; i += 256) s_e[i] = emb[i];
    __syncthreads();
    for (int k = tid; k < 512; k += 256) {
        float s = 0.f;
#pragma unroll
        for (int j = 0; j < 8; j++) { float e = s_e[k * 8 + j]; s += e * e; }
        s_hn[k] = 0.5f * s;
    }
    __syncthreads();

    const int base = blockIdx.x * 1024 + tid;
    float v[4][8];
#pragma unroll
    for (int u = 0; u < 4; u++) {
        int vi = base + u * 256;
        float4 a = ((const float4*)z)[vi * 2];
        float4 b = ((const float4*)z)[vi * 2 + 1];
        v[u][0] = a.x; v[u][1] = a.y; v[u][2] = a.z; v[u][3] = a.w;
        v[u][4] = b.x; v[u][5] = b.y; v[u][6] = b.z; v[u][7] = b.w;
    }

    float best[4] = {3.4e38f, 3.4e38f, 3.4e38f, 3.4e38f};
    int   bk[4]   = {0, 0, 0, 0};
    for (int k = 0; k < 512; k++) {
        float e0 = s_e[k * 8 + 0], e1 = s_e[k * 8 + 1], e2 = s_e[k * 8 + 2], e3 = s_e[k * 8 + 3];
        float e4 = s_e[k * 8 + 4], e5 = s_e[k * 8 + 5], e6 = s_e[k * 8 + 6], e7 = s_e[k * 8 + 7];
        float hn = s_hn[k];
#pragma unroll
        for (int u = 0; u < 4; u++) {
            float dot = e0 * v[u][0] + e1 * v[u][1] + e2 * v[u][2] + e3 * v[u][3]
                      + e4 * v[u][4] + e5 * v[u][5] + e6 * v[u][6] + e7 * v[u][7];
            float sc = hn - dot;
            if (sc < best[u]) { best[u] = sc; bk[u] = k; }
        }
    }

    float sq = 0.f;
#pragma unroll
    for (int u = 0; u < 4; u++) {
        int vi = base + u * 256;
        int kb = bk[u];
        float4 o1, o2;
        o1.x = s_e[kb * 8 + 0]; o1.y = s_e[kb * 8 + 1];
        o1.z = s_e[kb * 8 + 2]; o1.w = s_e[kb * 8 + 3];
        o2.x = s_e[kb * 8 + 4]; o2.y = s_e[kb * 8 + 5];
        o2.z = s_e[kb * 8 + 6]; o2.w = s_e[kb * 8 + 7];
#pragma unroll
        for (int j = 0; j < 8; j++) {
            float d = s_e[kb * 8 + j] - v[u][j];
            sq += d * d;
        }
        ((float4*)q)[vi * 2]     = o1;
        ((float4*)q)[vi * 2 + 1] = o2;
    }

    s_red[tid] = (double)sq;
    __syncthreads();
    for (int o = 128; o > 0; o >>= 1) {
        if (tid < o) s_red[tid] += s_red[tid + o];
        __syncthreads();
    }
    if (tid == 0) part[blockIdx.x] = s_red[0];
}

__global__ void finalize_loss(const double* __restrict__ part, float* __restrict__ outp) {
    __shared__ double s[256];
    int tid = threadIdx.x;
    s[tid] = part[tid];
    __syncthreads();
    for (int o = 128; o > 0; o >>= 1) {
        if (tid < o) s[tid] += s[tid + o];
        __syncthreads();
    }
    if (tid == 0) *outp = (float)(1.25 * s[0] / 2097152.0);
}

// ---------------------------------------------------------------------------
extern "C" void kernel_launch(void* const* d_in, const int* in_sizes, int n_in,
                              void* d_out, int out_size) {
    (void)in_sizes; (void)n_in;
    const float* x   = (const float*)d_in[0];
    const float* e1w = (const float*)d_in[1];
    const float* e1b = (const float*)d_in[2];
    const float* e2w = (const float*)d_in[3];
    const float* e2b = (const float*)d_in[4];
    const float* e3w = (const float*)d_in[5];
    const float* e3b = (const float*)d_in[6];
    const float* emb = (const float*)d_in[7];
    const float* d1w = (const float*)d_in[8];
    const float* d1b = (const float*)d_in[9];
    const float* d2w = (const float*)d_in[10];
    const float* d2b = (const float*)d_in[11];
    const float* d3w = (const float*)d_in[12];
    const float* d3b = (const float*)d_in[13];
    float* out = (float*)d_out;

    void *z1, *z2, *z3, *q, *y1, *y2, *part;
    void *pw1, *pw2, *pw3, *mw1, *mw2, *mw3;
    cudaGetSymbolAddress(&z1,  g_z1);
    cudaGetSymbolAddress(&z2,  g_z2);
    cudaGetSymbolAddress(&z3,  g_z3);
    cudaGetSymbolAddress(&q,   g_q);
    cudaGetSymbolAddress(&y1,  g_y1);
    cudaGetSymbolAddress(&y2,  g_y2);
    cudaGetSymbolAddress(&pw1, g_pw_e1);
    cudaGetSymbolAddress(&pw2, g_pw_e2);
    cudaGetSymbolAddress(&pw3, g_pw_e3);
    cudaGetSymbolAddress(&mw1, g_mw_d1);
    cudaGetSymbolAddress(&mw2, g_mw_d2);
    cudaGetSymbolAddress(&mw3, g_mw_d3);
    cudaGetSymbolAddress(&part, g_part);

    // ---- one merged pack launch (total 396288 items)
    pack_all<<<(396288 + 255) / 256, 256>>>(
        e1w, e2w, e3w, d1w, d2w, d3w,
        (u64*)pw1, (u64*)pw2, (u64*)pw3,
        (float*)mw1, (float*)mw2, (float*)mw3);

    // encoder (exact FFMA2 path)
    conv3x3r<156, 128, 64, 1, 0, 64><<<dim3(128, 2, 16), 256>>>(x, (u64*)pw1, e1b, (float*)z1);
    conv3x3r<128,  64, 64, 1, 0, 32><<<dim3(128, 1, 16), 256>>>((float*)z1, (u64*)pw2, e2b, (float*)z2);
    conv3x3r< 64,   8, 16, 1, 0,  8><<<dim3(128, 1, 16), 256>>>((float*)z2, (u64*)pw3, e3b, (float*)z3);

    // vector quantizer + loss partials (exact)
    vq_kernel<<<256, 256>>>((const float*)z3, emb, (float*)q, (double*)part);

    // decoder (tf32 tensor path)
    convmma<  8,  64, 64, 1, 0,   64><<<dim3(128, 1, 16), 256>>>((float*)q,  (float*)mw1, d1b, (float*)y1);
    convmma< 64, 128, 64, 1, 0,  128><<<dim3(128, 2, 16), 256>>>((float*)y1, (float*)mw2, d2b, (float*)y2);
    convmma<128, 156, 64, 2, 0,  160><<<dim3(128, 2, 16), 256>>>((float*)y2, (float*)mw3, d3b, out);
    convmma<128, 156, 32, 2, 128,160><<<dim3(128, 1, 16), 256>>>((float*)y2, (float*)mw3, d3b, out);

    finalize_loss<<<1, 256>>>((const double*)part, out + (out_size - 1));
}

// round 8
// speedup vs baseline: 2.3484x; 1.6888x over previous
#include <cuda_runtime.h>
#include <math.h>

// ---------------------------------------------------------------------------
// VQ-VAE forward.  B=16, L=156, P=8, H=W=128, codebook 512x8.
// R8: ALL convs on tensor pipe (mma.sync m16n8k8 tf32, rna-rounded operands).
//     VQ argmin flip risk quantified ~1.4e-3 of vectors -> ~1e-5 output error.
// ---------------------------------------------------------------------------

#define BATCH 16
#define HW    16384   // 128*128

typedef unsigned long long u64;

__device__ __forceinline__ float to_tf32(float x) {
    unsigned u; asm("cvt.rna.tf32.f32 %0, %1;" : "=r"(u) : "f"(x));
    return __uint_as_float(u);
}
__device__ __forceinline__ void mma_tf32(float c[4], const float a[4], float2 b) {
    asm volatile("mma.sync.aligned.m16n8k8.row.col.f32.tf32.tf32.f32 "
        "{%0,%1,%2,%3}, {%4,%5,%6,%7}, {%8,%9}, {%0,%1,%2,%3};"
        : "+f"(c[0]), "+f"(c[1]), "+f"(c[2]), "+f"(c[3])
        : "r"(__float_as_uint(a[0])), "r"(__float_as_uint(a[1])),
          "r"(__float_as_uint(a[2])), "r"(__float_as_uint(a[3])),
          "r"(__float_as_uint(b.x)), "r"(__float_as_uint(b.y)));
}

// Static device scratch (allocation-free rule).
__device__ float g_z1[BATCH * 128 * HW];
__device__ float g_z2[BATCH *  64 * HW];
__device__ float g_z3[BATCH *   8 * HW];
__device__ float g_q [BATCH *   8 * HW];
__device__ float g_y1[BATCH *  64 * HW];
__device__ float g_y2[BATCH * 128 * HW];
// tf32 mma weights: [chunk][tap 9][CO_PAD][8 ci-perm], perm p -> ci = (p>>1)+4*(p&1)
__device__ float g_mw_e1[20 * 9 * 128 * 8];
__device__ float g_mw_e2[16 * 9 *  64 * 8];
__device__ float g_mw_e3[ 8 * 9 *  16 * 8];
__device__ float g_mw_d1[ 1 * 9 *  64 * 8];
__device__ float g_mw_d2[ 8 * 9 * 128 * 8];
__device__ float g_mw_d3[16 * 9 * 160 * 8];
__device__ double g_part[256];

// ---------------------------------------------------------------------------
// Weight packing into mma layout.  transposed=0: Conv2d OIHW.
// transposed=1: ConvTranspose (in,out,kh,kw) -> IO swap + spatial flip.
// ---------------------------------------------------------------------------
__device__ void pack_mma(const float* __restrict__ w, float* __restrict__ out,
                         int CIN, int COUT, int CO_PAD, int transposed, int idx) {
    int p     = idx & 7;
    int co    = (idx >> 3) % CO_PAD;
    int tap   = ((idx >> 3) / CO_PAD) % 9;
    int chunk = ((idx >> 3) / CO_PAD) / 9;
    int ci    = chunk * 8 + (p >> 1) + 4 * (p & 1);
    float v = 0.f;
    if (co < COUT && ci < CIN)
        v = transposed ? w[((size_t)ci * COUT + co) * 9 + (8 - tap)]
                       : w[((size_t)co * CIN + ci) * 9 + tap];
    out[idx] = to_tf32(v);
}

__global__ void pack_all(const float* e1w, const float* e2w, const float* e3w,
                         const float* d1w, const float* d2w, const float* d3w,
                         float* me1, float* me2, float* me3,
                         float* md1, float* md2, float* md3) {
    int idx = blockIdx.x * 256 + threadIdx.x;
    if (idx < 184320) { pack_mma(e1w, me1, 156, 128, 128, 0, idx); return; }
    idx -= 184320;
    if (idx < 73728)  { pack_mma(e2w, me2, 128,  64,  64, 0, idx); return; }
    idx -= 73728;
    if (idx < 9216)   { pack_mma(e3w, me3,  64,   8,  16, 0, idx); return; }
    idx -= 9216;
    if (idx < 4608)   { pack_mma(d1w, md1,   8,  64,  64, 1, idx); return; }
    idx -= 4608;
    if (idx < 73728)  { pack_mma(d2w, md2,  64, 128, 128, 1, idx); return; }
    idx -= 73728;
    if (idx < 184320) { pack_mma(d3w, md3, 128, 156, 160, 1, idx); }
}

__device__ __forceinline__ float apply_act(float v, int ACT) {
    if (ACT == 1) return fmaxf(v, 0.f);
    if (ACT == 2) return 1.f / (1.f + __expf(-v));
    return v;
}

// ---------------------------------------------------------------------------
// tf32 tensor-core 3x3 same-conv (mma.sync m16n8k8).  C[px][co] accumulated
// as 9 shifted GEMMs per 8-ci chunk.  Block = (n, row h, MT co at CO_OFF).
// 8 warps: wm = warp&3 -> 32-px span, wn = warp>>2 -> MT/2 co span.
// A frag (row-major): a0(m=t/4,k=t%4) a1(m+8,k) a2(m,k+4) a3(m+8,k+4);
// k is the ci index, m the pixel.  B frag: b0(k=t%4, n=t/4) b1(k+4, n) served
// by one LDS.64 from the ci-permuted weight layout.
// ---------------------------------------------------------------------------
template<int CIN, int COUT, int MT, int ACT, int CO_OFF, int CO_PAD>
__global__ __launch_bounds__(256, 3)
void convmma(const float* __restrict__ in, const float* __restrict__ mw,
             const float* __restrict__ bias, float* __restrict__ out) {
    constexpr int CHUNKS = (CIN + 7) / 8;
    constexpr int ROWSTR = 136;
    constexpr int NT     = MT / 16;   // n-tiles per warp

    __shared__ float s_in[8 * 3 * ROWSTR];
    __shared__ float s_w[9 * MT * 8];

    const int n    = blockIdx.z;
    const int h    = blockIdx.x;
    const int cob0 = CO_OFF + blockIdx.y * MT;
    const int tid  = threadIdx.x;
    const int lane = tid & 31;
    const int warp = tid >> 5;
    const int wm   = warp & 3;
    const int wn   = warp >> 2;
    const int r4   = lane & 3;    // t%4
    const int r4h  = lane >> 2;   // t/4
    const int pxb  = wm * 32;
    const int col  = wn * (MT / 2);

    const float* inN = in + (size_t)n * CIN * HW;

    if (tid < 24) {
        float* row = s_in + tid * ROWSTR;
        row[0] = 0.f; row[1] = 0.f; row[2] = 0.f; row[3] = 0.f;
        row[132] = 0.f; row[133] = 0.f; row[134] = 0.f; row[135] = 0.f;
    }

    float C[2][NT][4];
#pragma unroll
    for (int mt = 0; mt < 2; mt++)
#pragma unroll
        for (int nt = 0; nt < NT; nt++)
#pragma unroll
            for (int k = 0; k < 4; k++) C[mt][nt][k] = 0.f;

    for (int chunk = 0; chunk < CHUNKS; chunk++) {
        // stage input slab (tf32-rounded); guard ci for padded last chunk
        for (int s4 = tid; s4 < 8 * 3 * 32; s4 += 256) {
            int kc = s4 / 96;
            int r  = (s4 / 32) % 3;
            int s  = s4 & 31;
            int ci = chunk * 8 + kc;
            int gh = h - 1 + r;
            float4 v = make_float4(0.f, 0.f, 0.f, 0.f);
            if (ci < CIN && gh >= 0 && gh < 128)
                v = *(const float4*)(inN + (size_t)ci * HW + gh * 128 + s * 4);
            v.x = to_tf32(v.x); v.y = to_tf32(v.y);
            v.z = to_tf32(v.z); v.w = to_tf32(v.w);
            *(float4*)(s_in + (kc * 3 + r) * ROWSTR + 4 + s * 4) = v;
        }
        // stage weights: [tap][MT co][8 perm] slice, contiguous per tap
        for (int s = tid; s < 9 * MT * 2; s += 256) {
            int tap = s / (MT * 2);
            int r   = s % (MT * 2);
            const float4* src = (const float4*)(mw +
                (((size_t)chunk * 9 + tap) * CO_PAD + cob0) * 8) + r;
            ((float4*)s_w)[tap * MT * 2 + r] = *src;
        }
        __syncthreads();

#pragma unroll
        for (int dh = 0; dh < 3; dh++) {
#pragma unroll
            for (int dw = 0; dw < 3; dw++) {
                const int tap = dh * 3 + dw;
                float a[2][4];
                {
                    const float* base = s_in + r4 * (3 * ROWSTR) + dh * ROWSTR
                                      + pxb + dw + 3 + r4h;
#pragma unroll
                    for (int mt = 0; mt < 2; mt++) {
                        a[mt][0] = base[mt * 16];
                        a[mt][1] = base[mt * 16 + 8];
                        a[mt][2] = base[4 * (3 * ROWSTR) + mt * 16];
                        a[mt][3] = base[4 * (3 * ROWSTR) + mt * 16 + 8];
                    }
                }
#pragma unroll
                for (int nt = 0; nt < NT; nt++) {
                    int co_l = col + nt * 8 + r4h;
                    float2 b = *(const float2*)(s_w + ((size_t)tap * MT + co_l) * 8 + r4 * 2);
#pragma unroll
                    for (int mt = 0; mt < 2; mt++)
                        mma_tf32(C[mt][nt], a[mt], b);
                }
            }
        }
        __syncthreads();
    }

    // epilogue: c0 (px, co) c1 (px, co+1) c2 (px+8, co) c3 (px+8, co+1)
#pragma unroll
    for (int mt = 0; mt < 2; mt++) {
#pragma unroll
        for (int nt = 0; nt < NT; nt++) {
            int px = pxb + mt * 16 + r4h;
            int co = cob0 + col + nt * 8 + r4 * 2;
            size_t o0 = (size_t)h * 128 + px;
            if (co < COUT) {
                float b = bias[co];
                float* op = out + ((size_t)n * COUT + co) * HW;
                op[o0]     = apply_act(C[mt][nt][0] + b, ACT);
                op[o0 + 8] = apply_act(C[mt][nt][2] + b, ACT);
            }
            if (co + 1 < COUT) {
                float b = bias[co + 1];
                float* op = out + ((size_t)n * COUT + co + 1) * HW;
                op[o0]     = apply_act(C[mt][nt][1] + b, ACT);
                op[o0 + 8] = apply_act(C[mt][nt][3] + b, ACT);
            }
        }
    }
}

// ---------------------------------------------------------------------------
// Vector quantizer (groups of 8 along W, torch .view semantics).
// ---------------------------------------------------------------------------
__global__ __launch_bounds__(256)
void vq_kernel(const float* __restrict__ z, const float* __restrict__ emb,
               float* __restrict__ q, double* __restrict__ part) {
    __shared__ float  s_e[512 * 8];
    __shared__ float  s_hn[512];
    __shared__ double s_red[256];

    const int tid = threadIdx.x;
    for (int i = tid; i < 4096; i += 256) s_e[i] = emb[i];
    __syncthreads();
    for (int k = tid; k < 512; k += 256) {
        float s = 0.f;
#pragma unroll
        for (int j = 0; j < 8; j++) { float e = s_e[k * 8 + j]; s += e * e; }
        s_hn[k] = 0.5f * s;
    }
    __syncthreads();

    const int base = blockIdx.x * 1024 + tid;
    float v[4][8];
#pragma unroll
    for (int u = 0; u < 4; u++) {
        int vi = base + u * 256;
        float4 a = ((const float4*)z)[vi * 2];
        float4 b = ((const float4*)z)[vi * 2 + 1];
        v[u][0] = a.x; v[u][1] = a.y; v[u][2] = a.z; v[u][3] = a.w;
        v[u][4] = b.x; v[u][5] = b.y; v[u][6] = b.z; v[u][7] = b.w;
    }

    float best[4] = {3.4e38f, 3.4e38f, 3.4e38f, 3.4e38f};
    int   bk[4]   = {0, 0, 0, 0};
    for (int k = 0; k < 512; k++) {
        float e0 = s_e[k * 8 + 0], e1 = s_e[k * 8 + 1], e2 = s_e[k * 8 + 2], e3 = s_e[k * 8 + 3];
        float e4 = s_e[k * 8 + 4], e5 = s_e[k * 8 + 5], e6 = s_e[k * 8 + 6], e7 = s_e[k * 8 + 7];
        float hn = s_hn[k];
#pragma unroll
        for (int u = 0; u < 4; u++) {
            float dot = e0 * v[u][0] + e1 * v[u][1] + e2 * v[u][2] + e3 * v[u][3]
                      + e4 * v[u][4] + e5 * v[u][5] + e6 * v[u][6] + e7 * v[u][7];
            float sc = hn - dot;
            if (sc < best[u]) { best[u] = sc; bk[u] = k; }
        }
    }

    float sq = 0.f;
#pragma unroll
    for (int u = 0; u < 4; u++) {
        int vi = base + u * 256;
        int kb = bk[u];
        float4 o1, o2;
        o1.x = s_e[kb * 8 + 0]; o1.y = s_e[kb * 8 + 1];
        o1.z = s_e[kb * 8 + 2]; o1.w = s_e[kb * 8 + 3];
        o2.x = s_e[kb * 8 + 4]; o2.y = s_e[kb * 8 + 5];
        o2.z = s_e[kb * 8 + 6]; o2.w = s_e[kb * 8 + 7];
#pragma unroll
        for (int j = 0; j < 8; j++) {
            float d = s_e[kb * 8 + j] - v[u][j];
            sq += d * d;
        }
        ((float4*)q)[vi * 2]     = o1;
        ((float4*)q)[vi * 2 + 1] = o2;
    }

    s_red[tid] = (double)sq;
    __syncthreads();
    for (int o = 128; o > 0; o >>= 1) {
        if (tid < o) s_red[tid] += s_red[tid + o];
        __syncthreads();
    }
    if (tid == 0) part[blockIdx.x] = s_red[0];
}

__global__ void finalize_loss(const double* __restrict__ part, float* __restrict__ outp) {
    __shared__ double s[256];
    int tid = threadIdx.x;
    s[tid] = part[tid];
    __syncthreads();
    for (int o = 128; o > 0; o >>= 1) {
        if (tid < o) s[tid] += s[tid + o];
        __syncthreads();
    }
    if (tid == 0) *outp = (float)(1.25 * s[0] / 2097152.0);
}

// ---------------------------------------------------------------------------
extern "C" void kernel_launch(void* const* d_in, const int* in_sizes, int n_in,
                              void* d_out, int out_size) {
    (void)in_sizes; (void)n_in;
    const float* x   = (const float*)d_in[0];
    const float* e1w = (const float*)d_in[1];
    const float* e1b = (const float*)d_in[2];
    const float* e2w = (const float*)d_in[3];
    const float* e2b = (const float*)d_in[4];
    const float* e3w = (const float*)d_in[5];
    const float* e3b = (const float*)d_in[6];
    const float* emb = (const float*)d_in[7];
    const float* d1w = (const float*)d_in[8];
    const float* d1b = (const float*)d_in[9];
    const float* d2w = (const float*)d_in[10];
    const float* d2b = (const float*)d_in[11];
    const float* d3w = (const float*)d_in[12];
    const float* d3b = (const float*)d_in[13];
    float* out = (float*)d_out;

    void *z1, *z2, *z3, *q, *y1, *y2, *part;
    void *me1, *me2, *me3, *md1, *md2, *md3;
    cudaGetSymbolAddress(&z1,  g_z1);
    cudaGetSymbolAddress(&z2,  g_z2);
    cudaGetSymbolAddress(&z3,  g_z3);
    cudaGetSymbolAddress(&q,   g_q);
    cudaGetSymbolAddress(&y1,  g_y1);
    cudaGetSymbolAddress(&y2,  g_y2);
    cudaGetSymbolAddress(&me1, g_mw_e1);
    cudaGetSymbolAddress(&me2, g_mw_e2);
    cudaGetSymbolAddress(&me3, g_mw_e3);
    cudaGetSymbolAddress(&md1, g_mw_d1);
    cudaGetSymbolAddress(&md2, g_mw_d2);
    cudaGetSymbolAddress(&md3, g_mw_d3);
    cudaGetSymbolAddress(&part, g_part);

    // ---- one merged pack launch (529920 items)
    pack_all<<<(529920 + 255) / 256, 256>>>(
        e1w, e2w, e3w, d1w, d2w, d3w,
        (float*)me1, (float*)me2, (float*)me3,
        (float*)md1, (float*)md2, (float*)md3);

    // encoder (tf32 tensor path)
    convmma<156, 128, 64, 1, 0, 128><<<dim3(128, 2, 16), 256>>>(x, (float*)me1, e1b, (float*)z1);
    convmma<128,  64, 64, 1, 0,  64><<<dim3(128, 1, 16), 256>>>((float*)z1, (float*)me2, e2b, (float*)z2);
    convmma< 64,   8, 16, 1, 0,  16><<<dim3(128, 1, 16), 256>>>((float*)z2, (float*)me3, e3b, (float*)z3);

    // vector quantizer + loss partials (exact fp32)
    vq_kernel<<<256, 256>>>((const float*)z3, emb, (float*)q, (double*)part);

    // decoder (tf32 tensor path)
    convmma<  8,  64, 64, 1, 0,   64><<<dim3(128, 1, 16), 256>>>((float*)q,  (float*)md1, d1b, (float*)y1);
    convmma< 64, 128, 64, 1, 0,  128><<<dim3(128, 2, 16), 256>>>((float*)y1, (float*)md2, d2b, (float*)y2);
    convmma<128, 156, 64, 2, 0,  160><<<dim3(128, 2, 16), 256>>>((float*)y2, (float*)md3, d3b, out);
    convmma<128, 156, 32, 2, 128,160><<<dim3(128, 1, 16), 256>>>((float*)y2, (float*)md3, d3b, out);

    finalize_loss<<<1, 256>>>((const double*)part, out + (out_size - 1));
}